// round 1
// baseline (speedup 1.0000x reference)
#include <cuda_runtime.h>

#define NB 32      // batch
#define NA 286     // atoms
#define CIN 23
#define HH 100     // hidden width of radial MLP
#define BPAD 288   // padded atom count (multiple of 32)

// ---------------- device scratch (no allocation allowed) ----------------
__device__ float  g_gT[NB][HH][BPAD];   // g[z][k][b] = sum_j rW2[k,j]*features[z,b,j]
__device__ float4 g_w1pack[HH];         // (rW1[0,k], rW1[1,k], rW1[2,k], rb1[k])
__device__ float  g_cz[NB];             // sum_{b,j} rb2[j]*features[z,b,j]
__device__ float  g_feats[NB][NA];      // conv output [B, N]

// ---------------- kernel A: precompute g (features @ rW2^T) ----------------
__global__ void __launch_bounds__(256) k_prep_g(const float* __restrict__ features,
                                                const float* __restrict__ rW2) {
    __shared__ float fs[32][CIN];          // features tile, stride 23 (odd -> conflict free)
    __shared__ float w2s[HH * CIN];
    const int z  = blockIdx.y;
    const int bt = blockIdx.x * 32;
    const int tid = threadIdx.x;

    for (int i = tid; i < 32 * CIN; i += 256) {
        int b = i / CIN, j = i % CIN;
        int gb = bt + b;
        fs[b][j] = (gb < NA) ? features[(z * NA + gb) * CIN + j] : 0.f;
    }
    for (int i = tid; i < HH * CIN; i += 256) w2s[i] = rW2[i];
    __syncthreads();

    for (int i = tid; i < HH * 32; i += 256) {
        int k = i >> 5, b = i & 31;
        float s = 0.f;
        #pragma unroll
        for (int j = 0; j < CIN; j++) s = fmaf(w2s[k * CIN + j], fs[b][j], s);
        g_gT[z][k][bt + b] = s;            // pad columns get 0 (fs zero-filled)
    }
}

// ---------------- kernel A2: cz per z + pack W1 ----------------
__global__ void __launch_bounds__(256) k_prep_aux(const float* __restrict__ features,
                                                  const float* __restrict__ rb2,
                                                  const float* __restrict__ rW1,
                                                  const float* __restrict__ rb1) {
    const int z = blockIdx.x;
    const int tid = threadIdx.x;
    if (z == 0 && tid < HH) {
        g_w1pack[tid] = make_float4(rW1[tid], rW1[HH + tid], rW1[2 * HH + tid], rb1[tid]);
    }
    __shared__ float red[256];
    float s = 0.f;
    const int TOT = NA * CIN;
    for (int i = tid; i < TOT; i += 256)
        s = fmaf(rb2[i % CIN], features[z * TOT + i], s);
    red[tid] = s;
    __syncthreads();
    for (int off = 128; off; off >>= 1) {
        if (tid < off) red[tid] += red[tid + off];
        __syncthreads();
    }
    if (tid == 0) g_cz[z] = red[0];
}

// ---------------- basis: cos(pi/2 * t) via even Taylor poly (no MUFU) ----------------
__device__ __forceinline__ float cospi_half(float t) {
    float y = t * t;
    float p = fmaf(9.1926027e-4f, y, -2.0863481e-2f);
    p = fmaf(p, y,  2.5366951e-1f);
    p = fmaf(p, y, -1.2337006f);
    p = fmaf(p, y,  1.0f);
    return p;
}

__device__ __forceinline__ void basis3(float r, float& p0, float& p1, float& p2) {
    // radii = {0, 1.5, 3.0}, step = 1.5 ; t_i = 1 - relu(2 - relu((r-rad_i)/step + 1))
    const float inv = 1.0f / 1.5f;
    float zz = r * inv;
    float t0 = 1.f - fmaxf(2.f - fmaxf(zz + 1.f, 0.f), 0.f);
    float t1 = 1.f - fmaxf(2.f - fmaxf(zz,       0.f), 0.f);
    float t2 = 1.f - fmaxf(2.f - fmaxf(zz - 1.f, 0.f), 0.f);
    p0 = cospi_half(t0);
    p1 = cospi_half(t1);
    p2 = cospi_half(t2);
}

// ---------------- main kernel: per-pair radial MLP + contraction ----------------
// Block: 256 threads = 8 warps; each warp owns 2 'a' rows (16 a per block).
// Lane = b within a 32-wide b-tile. g tile [k][b] in smem, W1 float4 broadcast.
__global__ void __launch_bounds__(256) k_main(const float* __restrict__ geometry) {
    const int z    = blockIdx.y;
    const int warp = threadIdx.x >> 5;
    const int lane = threadIdx.x & 31;
    const int tid  = threadIdx.x;
    const int aA   = blockIdx.x * 16 + warp * 2;
    const int aB   = aA + 1;

    __shared__ float4 w1s[HH];
    __shared__ float  gs[HH][32];
    __shared__ float  gbx[32], gby[32], gbz[32];

    for (int i = tid; i < HH; i += 256) w1s[i] = g_w1pack[i];

    float axA = 0.f, ayA = 0.f, azA = 0.f;
    float axB = 0.f, ayB = 0.f, azB = 0.f;
    if (aA < NA) { const float* p = geometry + (z * NA + aA) * 3; axA = p[0]; ayA = p[1]; azA = p[2]; }
    if (aB < NA) { const float* p = geometry + (z * NA + aB) * 3; axB = p[0]; ayB = p[1]; azB = p[2]; }

    float accA = 0.f, accB = 0.f;

    for (int bt = 0; bt < NA; bt += 32) {
        __syncthreads();   // also covers w1s on first pass / prior tile consumption
        for (int i = tid; i < HH * 32; i += 256) {
            int k = i >> 5, b = i & 31;
            gs[k][b] = g_gT[z][k][bt + b];
        }
        if (tid < 32) {
            int b = bt + tid;
            float x = 0.f, y = 0.f, w = 0.f;
            if (b < NA) { const float* p = geometry + (z * NA + b) * 3; x = p[0]; y = p[1]; w = p[2]; }
            gbx[tid] = x; gby[tid] = y; gbz[tid] = w;
        }
        __syncthreads();

        const float bx = gbx[lane], by = gby[lane], bz = gbz[lane];

        float p0A, p1A, p2A, p0B, p1B, p2B;
        {
            float dx = bx - axA, dy = by - ayA, dz = bz - azA;
            float r = sqrtf(fmaf(dx, dx, fmaf(dy, dy, fmaf(dz, dz, 1e-12f))));
            basis3(r, p0A, p1A, p2A);
        }
        {
            float dx = bx - axB, dy = by - ayB, dz = bz - azB;
            float r = sqrtf(fmaf(dx, dx, fmaf(dy, dy, fmaf(dz, dz, 1e-12f))));
            basis3(r, p0B, p1B, p2B);
        }

        #pragma unroll 20
        for (int k = 0; k < HH; k++) {
            float4 w  = w1s[k];
            float  gv = gs[k][lane];   // zero for padded b -> contribution 0
            float hA = fmaxf(fmaf(w.z, p2A, fmaf(w.y, p1A, fmaf(w.x, p0A, w.w))), 0.f);
            accA = fmaf(hA, gv, accA);
            float hB = fmaxf(fmaf(w.z, p2B, fmaf(w.y, p1B, fmaf(w.x, p0B, w.w))), 0.f);
            accB = fmaf(hB, gv, accB);
        }
    }

    #pragma unroll
    for (int off = 16; off; off >>= 1) {
        accA += __shfl_xor_sync(0xffffffffu, accA, off);
        accB += __shfl_xor_sync(0xffffffffu, accB, off);
    }

    if (lane == 0) {
        const float SCALE = 0.28209479177387814f / sqrtf(286.0f);  // Y0 / sqrt(N)
        float cz = g_cz[z];
        if (aA < NA) g_feats[z][aA] = (accA + cz) * SCALE;
        if (aB < NA) g_feats[z][aB] = (accB + cz) * SCALE;
    }
}

// ---------------- head MLP: 286 -> 30 -> 10 -> 1, one warp per z ----------------
__global__ void __launch_bounds__(32) k_head(const float* __restrict__ fc1W,
                                             const float* __restrict__ fc1b,
                                             const float* __restrict__ fc2W,
                                             const float* __restrict__ fc2b,
                                             const float* __restrict__ fc3W,
                                             const float* __restrict__ fc3b,
                                             float* __restrict__ out) {
    const int z = blockIdx.x;
    const int lane = threadIdx.x;
    __shared__ float fsh[NA];
    __shared__ float h1[30];
    __shared__ float h2[10];

    for (int i = lane; i < NA; i += 32) fsh[i] = g_feats[z][i];
    __syncwarp();

    if (lane < 30) {
        float s = fc1b[lane];
        for (int i = 0; i < NA; i++) s = fmaf(fsh[i], fc1W[i * 30 + lane], s);
        h1[lane] = fmaxf(s, 0.f);
    }
    __syncwarp();

    if (lane < 10) {
        float s = fc2b[lane];
        #pragma unroll
        for (int o = 0; o < 30; o++) s = fmaf(h1[o], fc2W[o * 10 + lane], s);
        h2[lane] = fmaxf(s, 0.f);
    }
    __syncwarp();

    if (lane == 0) {
        float s = fc3b[0];
        #pragma unroll
        for (int p = 0; p < 10; p++) s = fmaf(h2[p], fc3W[p], s);
        out[z] = s;
    }
}

// ---------------- launch ----------------
extern "C" void kernel_launch(void* const* d_in, const int* in_sizes, int n_in,
                              void* d_out, int out_size) {
    // metadata order: x, features, geometry, rW1, rb1, rW2, rb2, fc1W, fc1b, fc2W, fc2b, fc3W, fc3b
    const float* features = (const float*)d_in[1];
    const float* geometry = (const float*)d_in[2];
    const float* rW1      = (const float*)d_in[3];
    const float* rb1      = (const float*)d_in[4];
    const float* rW2      = (const float*)d_in[5];
    const float* rb2      = (const float*)d_in[6];
    const float* fc1W     = (const float*)d_in[7];
    const float* fc1b     = (const float*)d_in[8];
    const float* fc2W     = (const float*)d_in[9];
    const float* fc2b     = (const float*)d_in[10];
    const float* fc3W     = (const float*)d_in[11];
    const float* fc3b     = (const float*)d_in[12];
    float* out = (float*)d_out;

    k_prep_g  <<<dim3(9,  NB), 256>>>(features, rW2);
    k_prep_aux<<<NB, 256>>>(features, rb2, rW1, rb1);
    k_main    <<<dim3(18, NB), 256>>>(geometry);
    k_head    <<<NB, 32>>>(fc1W, fc1b, fc2W, fc2b, fc3W, fc3b, out);
}

// round 2
// speedup vs baseline: 1.0317x; 1.0317x over previous
#include <cuda_runtime.h>

#define NB 32      // batch
#define NA 286     // atoms
#define CIN 23
#define HH 100     // hidden width of radial MLP
#define BPAD 288   // padded atom count (multiple of 32)

// ---------------- packed f32x2 helpers (sm_103a) ----------------
#define FMA2(d, a, b, c) \
    asm("fma.rn.f32x2 %0, %1, %2, %3;" : "=l"(d) : "l"(a), "l"(b), "l"(c))

__device__ __forceinline__ unsigned long long pk2(float lo, float hi) {
    unsigned long long d;
    asm("mov.b64 %0, {%1, %2};" : "=l"(d) : "r"(__float_as_uint(lo)), "r"(__float_as_uint(hi)));
    return d;
}
__device__ __forceinline__ void unpk2(unsigned long long v, float& lo, float& hi) {
    unsigned int l, h;
    asm("mov.b64 {%0, %1}, %2;" : "=r"(l), "=r"(h) : "l"(v));
    lo = __uint_as_float(l); hi = __uint_as_float(h);
}
__device__ __forceinline__ unsigned long long dup2(float w) {
    unsigned long long u = __float_as_uint(w);
    return (u << 32) | u;
}

// ---------------- device scratch ----------------
__device__ float      g_gT[NB][HH][BPAD];   // g[z][k][b] = sum_j rW2[k,j]*features[z,b,j]
__device__ ulonglong2 g_w1dup[HH][2];       // [k][0]={wx,wx | wy,wy}, [k][1]={wz,wz | wb,wb}
__device__ float      g_cz[NB];             // sum_{b,j} rb2[j]*features[z,b,j]
__device__ float      g_feats[NB][NA];      // conv output [B, N]

// ---------------- kernel A: precompute g (features @ rW2^T) ----------------
__global__ void __launch_bounds__(256) k_prep_g(const float* __restrict__ features,
                                                const float* __restrict__ rW2) {
    __shared__ float fs[32][CIN];
    __shared__ float w2s[HH * CIN];
    const int z  = blockIdx.y;
    const int bt = blockIdx.x * 32;
    const int tid = threadIdx.x;

    for (int i = tid; i < 32 * CIN; i += 256) {
        int b = i / CIN, j = i % CIN;
        int gb = bt + b;
        fs[b][j] = (gb < NA) ? features[(z * NA + gb) * CIN + j] : 0.f;
    }
    for (int i = tid; i < HH * CIN; i += 256) w2s[i] = rW2[i];
    __syncthreads();

    for (int i = tid; i < HH * 32; i += 256) {
        int k = i >> 5, b = i & 31;
        float s = 0.f;
        #pragma unroll
        for (int j = 0; j < CIN; j++) s = fmaf(w2s[k * CIN + j], fs[b][j], s);
        g_gT[z][k][bt + b] = s;
    }
}

// ---------------- kernel A2: cz per z + packed/duplicated W1 ----------------
__global__ void __launch_bounds__(256) k_prep_aux(const float* __restrict__ features,
                                                  const float* __restrict__ rb2,
                                                  const float* __restrict__ rW1,
                                                  const float* __restrict__ rb1) {
    const int z = blockIdx.x;
    const int tid = threadIdx.x;
    if (z == 0 && tid < HH) {
        float wx = rW1[tid], wy = rW1[HH + tid], wz = rW1[2 * HH + tid], wb = rb1[tid];
        g_w1dup[tid][0] = make_ulonglong2(dup2(wx), dup2(wy));
        g_w1dup[tid][1] = make_ulonglong2(dup2(wz), dup2(wb));
    }
    __shared__ float red[256];
    float s = 0.f;
    const int TOT = NA * CIN;
    for (int i = tid; i < TOT; i += 256)
        s = fmaf(rb2[i % CIN], features[z * TOT + i], s);
    red[tid] = s;
    __syncthreads();
    for (int off = 128; off; off >>= 1) {
        if (tid < off) red[tid] += red[tid + off];
        __syncthreads();
    }
    if (tid == 0) g_cz[z] = red[0];
}

// ---------------- basis: cos(pi/2 * t) via even poly (no MUFU cos) ----------------
__device__ __forceinline__ float cospi_half(float t) {
    float y = t * t;
    float p = fmaf(9.1926027e-4f, y, -2.0863481e-2f);
    p = fmaf(p, y,  2.5366951e-1f);
    p = fmaf(p, y, -1.2337006f);
    p = fmaf(p, y,  1.0f);
    return p;
}

__device__ __forceinline__ void basis3(float r, float& p0, float& p1, float& p2) {
    const float inv = 1.0f / 1.5f;
    float zz = r * inv;
    float t0 = 1.f - fmaxf(2.f - fmaxf(zz + 1.f, 0.f), 0.f);
    float t1 = 1.f - fmaxf(2.f - fmaxf(zz,       0.f), 0.f);
    float t2 = 1.f - fmaxf(2.f - fmaxf(zz - 1.f, 0.f), 0.f);
    p0 = cospi_half(t0);
    p1 = cospi_half(t1);
    p2 = cospi_half(t2);
}

// ---------------- main kernel: per-pair radial MLP + contraction ----------------
// 128 threads = 4 warps; each warp owns 4 'a' rows (2 packed f32x2 pairs).
// Lane = b within a 32-wide b-tile. grid = (18, NB) -> 16 a per block.
__global__ void __launch_bounds__(128) k_main(const float* __restrict__ geometry) {
    const int z    = blockIdx.y;
    const int warp = threadIdx.x >> 5;
    const int lane = threadIdx.x & 31;
    const int tid  = threadIdx.x;
    const int a0   = blockIdx.x * 16 + warp * 4;

    __shared__ ulonglong2 w1s2[HH][2];
    __shared__ float      gs[HH][32];
    __shared__ float      gb[3][32];

    for (int i = tid; i < HH * 2; i += 128)
        ((ulonglong2*)w1s2)[i] = ((const ulonglong2*)g_w1dup)[i];

    float ax[4], ay[4], az[4];
    #pragma unroll
    for (int u = 0; u < 4; u++) {
        int a = a0 + u; if (a > NA - 1) a = NA - 1;     // clamp; extra rows never written
        const float* p = geometry + (z * NA + a) * 3;
        ax[u] = p[0]; ay[u] = p[1]; az[u] = p[2];
    }

    float acc0 = 0.f, acc1 = 0.f, acc2 = 0.f, acc3 = 0.f;

    for (int bt = 0; bt < NA; bt += 32) {
        __syncthreads();
        for (int i = tid; i < HH * 32; i += 128)
            gs[i >> 5][i & 31] = g_gT[z][i >> 5][bt + (i & 31)];
        if (tid < 32) {
            int b = bt + tid;
            float x = 0.f, y = 0.f, w = 0.f;
            if (b < NA) { const float* p = geometry + (z * NA + b) * 3; x = p[0]; y = p[1]; w = p[2]; }
            gb[0][tid] = x; gb[1][tid] = y; gb[2][tid] = w;
        }
        __syncthreads();

        const float bx = gb[0][lane], by = gb[1][lane], bz = gb[2][lane];

        float P0[4], P1[4], P2[4];
        #pragma unroll
        for (int u = 0; u < 4; u++) {
            float dx = bx - ax[u], dy = by - ay[u], dz = bz - az[u];
            float r = sqrtf(fmaf(dx, dx, fmaf(dy, dy, fmaf(dz, dz, 1e-12f))));
            basis3(r, P0[u], P1[u], P2[u]);
        }
        // pack basis for the two a-pairs P={a0,a1}, Q={a2,a3}
        unsigned long long p0P = pk2(P0[0], P0[1]), p0Q = pk2(P0[2], P0[3]);
        unsigned long long p1P = pk2(P1[0], P1[1]), p1Q = pk2(P1[2], P1[3]);
        unsigned long long p2P = pk2(P2[0], P2[1]), p2Q = pk2(P2[2], P2[3]);

        #pragma unroll 10
        for (int k = 0; k < HH; k++) {
            ulonglong2 cA = w1s2[k][0];   // .x = {wx,wx}  .y = {wy,wy}
            ulonglong2 cB = w1s2[k][1];   // .x = {wz,wz}  .y = {wb,wb}
            unsigned long long tP, tQ;
            FMA2(tP, cA.x, p0P, cB.y);
            FMA2(tP, cA.y, p1P, tP);
            FMA2(tP, cB.x, p2P, tP);
            FMA2(tQ, cA.x, p0Q, cB.y);
            FMA2(tQ, cA.y, p1Q, tQ);
            FMA2(tQ, cB.x, p2Q, tQ);
            float gv = gs[k][lane];
            float h0, h1, h2, h3;
            unpk2(tP, h0, h1);
            unpk2(tQ, h2, h3);
            acc0 = fmaf(fmaxf(h0, 0.f), gv, acc0);
            acc1 = fmaf(fmaxf(h1, 0.f), gv, acc1);
            acc2 = fmaf(fmaxf(h2, 0.f), gv, acc2);
            acc3 = fmaf(fmaxf(h3, 0.f), gv, acc3);
        }
    }

    #pragma unroll
    for (int off = 16; off; off >>= 1) {
        acc0 += __shfl_xor_sync(0xffffffffu, acc0, off);
        acc1 += __shfl_xor_sync(0xffffffffu, acc1, off);
        acc2 += __shfl_xor_sync(0xffffffffu, acc2, off);
        acc3 += __shfl_xor_sync(0xffffffffu, acc3, off);
    }

    if (lane == 0) {
        const float SCALE = 0.28209479177387814f / sqrtf(286.0f);  // Y0 / sqrt(N)
        float cz = g_cz[z];
        float accs[4] = {acc0, acc1, acc2, acc3};
        #pragma unroll
        for (int u = 0; u < 4; u++) {
            int a = a0 + u;
            if (a < NA) g_feats[z][a] = (accs[u] + cz) * SCALE;
        }
    }
}

// ---------------- head MLP: 286 -> 30 -> 10 -> 1, one 256-thread block per z ----------------
__global__ void __launch_bounds__(256) k_head(const float* __restrict__ fc1W,
                                              const float* __restrict__ fc1b,
                                              const float* __restrict__ fc2W,
                                              const float* __restrict__ fc2b,
                                              const float* __restrict__ fc3W,
                                              const float* __restrict__ fc3b,
                                              float* __restrict__ out) {
    const int z = blockIdx.x;
    const int tid = threadIdx.x;
    const int warp = tid >> 5;
    const int lane = tid & 31;
    __shared__ float fsh[NA];
    __shared__ float h1[30];
    __shared__ float h2[10];

    for (int i = tid; i < NA; i += 256) fsh[i] = g_feats[z][i];
    __syncthreads();

    // fc1: warp-per-output, lanes parallel over the 286 inputs
    for (int o = warp; o < 30; o += 8) {
        float s = 0.f;
        for (int i = lane; i < NA; i += 32)
            s = fmaf(fsh[i], __ldg(&fc1W[i * 30 + o]), s);
        #pragma unroll
        for (int off = 16; off; off >>= 1) s += __shfl_xor_sync(0xffffffffu, s, off);
        if (lane == 0) h1[o] = fmaxf(s + fc1b[o], 0.f);
    }
    __syncthreads();

    if (tid < 10) {
        float s = fc2b[tid];
        #pragma unroll
        for (int o = 0; o < 30; o++) s = fmaf(h1[o], fc2W[o * 10 + tid], s);
        h2[tid] = fmaxf(s, 0.f);
    }
    __syncthreads();

    if (tid == 0) {
        float s = fc3b[0];
        #pragma unroll
        for (int p = 0; p < 10; p++) s = fmaf(h2[p], fc3W[p], s);
        out[z] = s;
    }
}

// ---------------- launch ----------------
extern "C" void kernel_launch(void* const* d_in, const int* in_sizes, int n_in,
                              void* d_out, int out_size) {
    const float* features = (const float*)d_in[1];
    const float* geometry = (const float*)d_in[2];
    const float* rW1      = (const float*)d_in[3];
    const float* rb1      = (const float*)d_in[4];
    const float* rW2      = (const float*)d_in[5];
    const float* rb2      = (const float*)d_in[6];
    const float* fc1W     = (const float*)d_in[7];
    const float* fc1b     = (const float*)d_in[8];
    const float* fc2W     = (const float*)d_in[9];
    const float* fc2b     = (const float*)d_in[10];
    const float* fc3W     = (const float*)d_in[11];
    const float* fc3b     = (const float*)d_in[12];
    float* out = (float*)d_out;

    k_prep_g  <<<dim3(9,  NB), 256>>>(features, rW2);
    k_prep_aux<<<NB, 256>>>(features, rb2, rW1, rb1);
    k_main    <<<dim3(18, NB), 128>>>(geometry);
    k_head    <<<NB, 256>>>(fc1W, fc1b, fc2W, fc2b, fc3W, fc3b, out);
}

// round 5
// speedup vs baseline: 1.0456x; 1.0134x over previous
#include <cuda_runtime.h>

#define NB 32      // batch
#define NA 286     // atoms
#define CIN 23
#define HH 100     // hidden width of radial MLP
#define BPAD 288   // padded atom count

// ---------------- packed f32x2 helpers (sm_103a) ----------------
#define FMA2(d, a, b, c) \
    asm("fma.rn.f32x2 %0, %1, %2, %3;" : "=l"(d) : "l"(a), "l"(b), "l"(c))
#define ADD2(d, a, b) \
    asm("add.rn.f32x2 %0, %1, %2;" : "=l"(d) : "l"(a), "l"(b))

__device__ __forceinline__ unsigned long long pk2(float lo, float hi) {
    unsigned long long d;
    asm("mov.b64 %0, {%1, %2};" : "=l"(d) : "r"(__float_as_uint(lo)), "r"(__float_as_uint(hi)));
    return d;
}
__device__ __forceinline__ void unpk2(unsigned long long v, float& lo, float& hi) {
    unsigned int l, h;
    asm("mov.b64 {%0, %1}, %2;" : "=r"(l), "=r"(h) : "l"(v));
    lo = __uint_as_float(l); hi = __uint_as_float(h);
}
__device__ __forceinline__ unsigned long long dup2(float w) {
    unsigned long long u = __float_as_uint(w);
    return (u << 32) | u;
}

// ---------------- device scratch ----------------
__device__ unsigned long long g_gT2[NB][HH][BPAD];  // dup {g,g} per (z,k,b)
__device__ ulonglong4        g_u[NB][BPAD];         // dup'd u0..u3 per (z,b): W1^T @ g[b] (+bias row)
__device__ ulonglong2        g_w1dup[HH][2];        // [k][0]={wx2,wy2} [k][1]={wz2,wb2}
__device__ float             g_cz[NB];
__device__ float4            g_geom4[NB][BPAD];     // (x,y,z,0), zero-padded
__device__ float             g_feats[NB][NA];

// ---------------- merged prep kernel ----------------
// grid (10, NB), 256 thr. bx<9: g-tile (32 b's) + per-b u vector. bx==9: cz, geom4, (z==0) w1 pack.
__global__ void __launch_bounds__(256) k_prep(const float* __restrict__ features,
                                              const float* __restrict__ geometry,
                                              const float* __restrict__ rW1,
                                              const float* __restrict__ rb1,
                                              const float* __restrict__ rW2,
                                              const float* __restrict__ rb2) {
    const int z = blockIdx.y;
    const int tid = threadIdx.x;

    if (blockIdx.x == 9) {
        // --- w1 pack (once) ---
        if (z == 0 && tid < HH) {
            float wx = rW1[tid], wy = rW1[HH + tid], wz = rW1[2 * HH + tid], wb = rb1[tid];
            g_w1dup[tid][0] = make_ulonglong2(dup2(wx), dup2(wy));
            g_w1dup[tid][1] = make_ulonglong2(dup2(wz), dup2(wb));
        }
        // --- padded geometry float4 ---
        for (int b = tid; b < BPAD; b += 256) {
            float4 v = make_float4(0.f, 0.f, 0.f, 0.f);
            if (b < NA) {
                const float* p = geometry + (z * NA + b) * 3;
                v.x = p[0]; v.y = p[1]; v.z = p[2];
            }
            g_geom4[z][b] = v;
        }
        // --- cz ---
        __shared__ float red[256];
        float s = 0.f;
        const int TOT = NA * CIN;
        for (int i = tid; i < TOT; i += 256)
            s = fmaf(rb2[i % CIN], features[z * TOT + i], s);
        red[tid] = s;
        __syncthreads();
        for (int off = 128; off; off >>= 1) {
            if (tid < off) red[tid] += red[tid + off];
            __syncthreads();
        }
        if (tid == 0) g_cz[z] = red[0];
        return;
    }

    // --- g tile + u ---
    __shared__ float fs[32][CIN];
    __shared__ float w2s[HH * CIN];
    __shared__ float gsh[HH][32];
    const int bt = blockIdx.x * 32;

    for (int i = tid; i < 32 * CIN; i += 256) {
        int b = i / CIN, j = i % CIN;
        int gb = bt + b;
        fs[b][j] = (gb < NA) ? features[(z * NA + gb) * CIN + j] : 0.f;
    }
    for (int i = tid; i < HH * CIN; i += 256) w2s[i] = rW2[i];
    __syncthreads();

    for (int i = tid; i < HH * 32; i += 256) {
        int k = i >> 5, b = i & 31;
        float s = 0.f;
        #pragma unroll
        for (int j = 0; j < CIN; j++) s = fmaf(w2s[k * CIN + j], fs[b][j], s);
        gsh[k][b] = s;
        g_gT2[z][k][bt + b] = dup2(s);
    }
    __syncthreads();

    // u_c[b] = sum_k wc[k] * g[b][k], c in {x,y,z,bias}
    if (tid < 128) {
        int b = tid & 31, c = tid >> 5;
        float acc = 0.f;
        for (int k = 0; k < HH; k++) {
            float w = (c < 3) ? __ldg(&rW1[c * HH + k]) : __ldg(&rb1[k]);
            acc = fmaf(w, gsh[k][b], acc);
        }
        ((unsigned long long*)&g_u[z][bt + b])[c] = dup2(acc);
    }
}

// ---------------- basis: cos(pi/2 * t) via even poly ----------------
__device__ __forceinline__ float cospi_half(float t) {
    float y = t * t;
    float p = fmaf(9.1926027e-4f, y, -2.0863481e-2f);
    p = fmaf(p, y,  2.5366951e-1f);
    p = fmaf(p, y, -1.2337006f);
    p = fmaf(p, y,  1.0f);
    return p;
}
__device__ __forceinline__ void basis3(float r, float& p0, float& p1, float& p2) {
    const float inv = 1.0f / 1.5f;
    float zz = r * inv;
    float t0 = 1.f - fmaxf(2.f - fmaxf(zz + 1.f, 0.f), 0.f);
    float t1 = 1.f - fmaxf(2.f - fmaxf(zz,       0.f), 0.f);
    float t2 = 1.f - fmaxf(2.f - fmaxf(zz - 1.f, 0.f), 0.f);
    p0 = cospi_half(t0);
    p1 = cospi_half(t1);
    p2 = cospi_half(t2);
}

// ---------------- main kernel ----------------
// 128 thr = 4 warps, 8 a's per warp (4 packed pairs), 32 a per block. grid (9, NB).
// relu split: sum_k relu(h)g = 0.5*(p~ . u[b]) + 0.5*sum_k |h|g ; both packed f32x2.
__global__ void __launch_bounds__(128) k_main() {
    const int z    = blockIdx.y;
    const int warp = threadIdx.x >> 5;
    const int lane = threadIdx.x & 31;
    const int tid  = threadIdx.x;
    const int a0   = blockIdx.x * 32 + warp * 8;

    __shared__ ulonglong2         w1s2[HH][2];
    __shared__ unsigned long long gs2[HH][32];

    for (int i = tid; i < HH * 2; i += 128)
        ((ulonglong2*)w1s2)[i] = ((const ulonglong2*)g_w1dup)[i];

    float ax[8], ay[8], az[8];
    #pragma unroll
    for (int u = 0; u < 8; u++) {
        int a = a0 + u; if (a > NA - 1) a = NA - 1;   // clamp; extras never written
        float4 p = g_geom4[z][a];
        ax[u] = p.x; ay[u] = p.y; az[u] = p.z;
    }

    unsigned long long acc[4];
    #pragma unroll
    for (int p = 0; p < 4; p++) acc[p] = 0ull;

    for (int bt = 0; bt < NA; bt += 32) {
        __syncthreads();   // protect gs2 reuse (and w1s2 on first pass)
        for (int i = tid; i < HH * 32; i += 128)
            gs2[i >> 5][i & 31] = g_gT2[z][i >> 5][bt + (i & 31)];
        __syncthreads();

        const float4 bg = g_geom4[z][bt + lane];
        const ulonglong4 ud = g_u[z][bt + lane];

        unsigned long long P0[4], P1[4], P2[4];
        #pragma unroll
        for (int p = 0; p < 4; p++) {
            float q0a, q1a, q2a, q0b, q1b, q2b;
            {
                float dx = bg.x - ax[2*p], dy = bg.y - ay[2*p], dz = bg.z - az[2*p];
                float r = sqrtf(fmaf(dx, dx, fmaf(dy, dy, fmaf(dz, dz, 1e-12f))));
                basis3(r, q0a, q1a, q2a);
            }
            {
                float dx = bg.x - ax[2*p+1], dy = bg.y - ay[2*p+1], dz = bg.z - az[2*p+1];
                float r = sqrtf(fmaf(dx, dx, fmaf(dy, dy, fmaf(dz, dz, 1e-12f))));
                basis3(r, q0b, q1b, q2b);
            }
            P0[p] = pk2(q0a, q0b); P1[p] = pk2(q1a, q1b); P2[p] = pk2(q2a, q2b);
            // linear half: p~ . u[b]  (bias row included via ud.w)
            unsigned long long lin;
            FMA2(lin, P0[p], ud.x, ud.w);
            FMA2(lin, P1[p], ud.y, lin);
            FMA2(lin, P2[p], ud.z, lin);
            ADD2(acc[p], acc[p], lin);
        }

        #pragma unroll 10
        for (int k = 0; k < HH; k++) {
            ulonglong2 cA = w1s2[k][0];   // {wx2, wy2}
            ulonglong2 cB = w1s2[k][1];   // {wz2, wb2}
            unsigned long long gd = gs2[k][lane];
            #pragma unroll
            for (int p = 0; p < 4; p++) {
                unsigned long long h;
                FMA2(h, cA.x, P0[p], cB.y);
                FMA2(h, cA.y, P1[p], h);
                FMA2(h, cB.x, P2[p], h);
                h &= 0x7FFFFFFF7FFFFFFFull;       // packed |h|
                FMA2(acc[p], h, gd, acc[p]);
            }
        }
    }

    float s[8];
    #pragma unroll
    for (int p = 0; p < 4; p++) unpk2(acc[p], s[2*p], s[2*p+1]);
    #pragma unroll
    for (int u = 0; u < 8; u++) {
        #pragma unroll
        for (int off = 16; off; off >>= 1)
            s[u] += __shfl_xor_sync(0xffffffffu, s[u], off);
    }

    if (lane == 0) {
        const float SCALE0 = 0.28209479177387814f / 16.911534525287763f;  // Y0 / sqrt(286)
        const float HALF_SCALE = 0.5f * SCALE0;
        float czs = g_cz[z] * SCALE0;
        #pragma unroll
        for (int u = 0; u < 8; u++) {
            int a = a0 + u;
            if (a < NA) g_feats[z][a] = fmaf(s[u], HALF_SCALE, czs);
        }
    }
}

// ---------------- head MLP: 286 -> 30 -> 10 -> 1 ----------------
__global__ void __launch_bounds__(256) k_head(const float* __restrict__ fc1W,
                                              const float* __restrict__ fc1b,
                                              const float* __restrict__ fc2W,
                                              const float* __restrict__ fc2b,
                                              const float* __restrict__ fc3W,
                                              const float* __restrict__ fc3b,
                                              float* __restrict__ out) {
    const int z = blockIdx.x;
    const int tid = threadIdx.x;
    const int warp = tid >> 5;
    const int lane = tid & 31;
    __shared__ float fsh[BPAD];
    __shared__ float h1[30];
    __shared__ float h2[10];

    for (int i = tid; i < BPAD; i += 256) fsh[i] = (i < NA) ? g_feats[z][i] : 0.f;
    __syncthreads();

    // fc1: warp-per-output; 9 independent prefetched loads -> MLP=9
    for (int o = warp; o < 30; o += 8) {
        float w[9], f[9];
        #pragma unroll
        for (int kk = 0; kk < 9; kk++) {
            int idx = lane + 32 * kk;
            w[kk] = (idx < NA) ? __ldg(&fc1W[idx * 30 + o]) : 0.f;
            f[kk] = fsh[idx];
        }
        float ssum = 0.f;
        #pragma unroll
        for (int kk = 0; kk < 9; kk++) ssum = fmaf(w[kk], f[kk], ssum);
        #pragma unroll
        for (int off = 16; off; off >>= 1) ssum += __shfl_xor_sync(0xffffffffu, ssum, off);
        if (lane == 0) h1[o] = fmaxf(ssum + fc1b[o], 0.f);
    }
    __syncthreads();

    if (tid < 10) {
        float s = fc2b[tid];
        #pragma unroll
        for (int o = 0; o < 30; o++) s = fmaf(h1[o], fc2W[o * 10 + tid], s);
        h2[tid] = fmaxf(s, 0.f);
    }
    __syncthreads();

    if (tid == 0) {
        float s = fc3b[0];
        #pragma unroll
        for (int p = 0; p < 10; p++) s = fmaf(h2[p], fc3W[p], s);
        out[z] = s;
    }
}

// ---------------- launch ----------------
extern "C" void kernel_launch(void* const* d_in, const int* in_sizes, int n_in,
                              void* d_out, int out_size) {
    const float* features = (const float*)d_in[1];
    const float* geometry = (const float*)d_in[2];
    const float* rW1      = (const float*)d_in[3];
    const float* rb1      = (const float*)d_in[4];
    const float* rW2      = (const float*)d_in[5];
    const float* rb2      = (const float*)d_in[6];
    const float* fc1W     = (const float*)d_in[7];
    const float* fc1b     = (const float*)d_in[8];
    const float* fc2W     = (const float*)d_in[9];
    const float* fc2b     = (const float*)d_in[10];
    const float* fc3W     = (const float*)d_in[11];
    const float* fc3b     = (const float*)d_in[12];
    float* out = (float*)d_out;

    k_prep <<<dim3(10, NB), 256>>>(features, geometry, rW1, rb1, rW2, rb2);
    k_main <<<dim3(9,  NB), 128>>>();
    k_head <<<NB, 256>>>(fc1W, fc1b, fc2W, fc2b, fc3W, fc3b, out);
}